// round 8
// baseline (speedup 1.0000x reference)
#include <cuda_runtime.h>
#include <cuda_bf16.h>
#include <cstdint>

// ---------------------------------------------------------------------------
// DistributedAttention, B=2, S=4096, H=1024 fp32.
// bf16x3 error-compensated mma.sync (a = hi + lo; hi*hi + hi*lo + lo*hi).
// All GEMMs NT: C[M,N] = alpha * A[M,K] @ B[N,K]^T (+bias).
// R8: CTA 128x128, 256 threads (8 warps, warp tile 64x32), 2-stage pipeline
//     at 40KB/stage -> 2 CTAs/SM (two independent barrier domains per SM to
//     cover sync/latency stalls that held tensor pipe at 54%).
// ---------------------------------------------------------------------------

#define BM 128
#define BN 128
#define KT 32
#define APITCH 80                        // bytes per 32-bf16 row (5x16B, bank-clean)
#define REGA (128 * APITCH)              // 10240 bytes per component
#define STAGE_BYTES (4 * REGA)           // Ahi|Alo|Bhi|Blo = 40960
#define GEMM_SMEM (2 * STAGE_BYTES)      // 81920 (2 stages) -> 2 CTAs/SM

typedef __nv_bfloat16 bf16;

// fp32 scratch
__device__ float g_v[8388608];          // v projection (fp32, pre-transpose)
__device__ float g_s[33554432];         // scores (fp32)
// split (hi/lo bf16) scratch
__device__ bf16 g_xh[8388608],  g_xl[8388608];
__device__ bf16 g_wqh[1048576], g_wql[1048576];
__device__ bf16 g_wkh[1048576], g_wkl[1048576];
__device__ bf16 g_wvh[1048576], g_wvl[1048576];
__device__ bf16 g_woh[1048576], g_wol[1048576];
__device__ bf16 g_qh[8388608],  g_ql[8388608];
__device__ bf16 g_kh[8388608],  g_kl[8388608];
__device__ bf16 g_vth[8388608], g_vtl[8388608];
__device__ bf16 g_wh[33554432], g_wl[33554432];   // softmax weights
__device__ bf16 g_ah[8388608],  g_al[8388608];    // attn output

__device__ __forceinline__ uint32_t smem_u32(const void* p) {
    uint32_t a;
    asm("{ .reg .u64 t; cvta.to.shared.u64 t, %1; cvt.u32.u64 %0, t; }" : "=r"(a) : "l"(p));
    return a;
}
__device__ __forceinline__ void cp16(uint32_t dst, const void* src) {
    asm volatile("cp.async.cg.shared.global [%0], [%1], 16;" :: "r"(dst), "l"(src));
}

#define LDSM4(r, addr) \
    asm volatile("ldmatrix.sync.aligned.m8n8.x4.shared.b16 {%0,%1,%2,%3}, [%4];" \
                 : "=r"((r)[0]), "=r"((r)[1]), "=r"((r)[2]), "=r"((r)[3]) : "r"(addr))

__device__ __forceinline__ void mma16(float* c, const uint32_t* a, const uint32_t* b) {
    asm volatile(
        "mma.sync.aligned.m16n8k16.row.col.f32.bf16.bf16.f32 "
        "{%0,%1,%2,%3}, {%4,%5,%6,%7}, {%8,%9}, {%0,%1,%2,%3};"
        : "+f"(c[0]), "+f"(c[1]), "+f"(c[2]), "+f"(c[3])
        : "r"(a[0]), "r"(a[1]), "r"(a[2]), "r"(a[3]), "r"(b[0]), "r"(b[1]));
}

// split pair (a=low element, b=high element) into packed bf16x2 hi / lo words
__device__ __forceinline__ void split2(float a, float b, uint32_t& hi2, uint32_t& lo2) {
    uint32_t ua = __float_as_uint(a) & 0xFFFF0000u;
    uint32_t ub = __float_as_uint(b) & 0xFFFF0000u;
    hi2 = (ua >> 16) | ub;
    __nv_bfloat162 l2 = __floats2bfloat162_rn(a - __uint_as_float(ua),
                                              b - __uint_as_float(ub));
    lo2 = *reinterpret_cast<uint32_t*>(&l2);
}

// ---------------------------------------------------------------------------
// bf16x3 NT GEMM. 256 threads, CTA 128x128, warp grid 2(m) x 4(n),
// warp tile 64x32. 2-stage cp.async pipeline, 2 CTAs/SM.
// ---------------------------------------------------------------------------
template <bool BIAS, bool SPLIT_OUT>
__global__ void __launch_bounds__(256, 2)
gemm_b3(const bf16* __restrict__ Ah, const bf16* __restrict__ Al,
        const bf16* __restrict__ Bh, const bf16* __restrict__ Bl,
        const float* __restrict__ bias, float* __restrict__ C,
        bf16* __restrict__ Chi, bf16* __restrict__ Clo,
        int M, int N, int K, float alpha,
        long long sA, long long sB, long long sC)
{
    extern __shared__ char sm[];
    const uint32_t smb = smem_u32(sm);

    Ah += (long long)blockIdx.z * sA;  Al += (long long)blockIdx.z * sA;
    Bh += (long long)blockIdx.z * sB;  Bl += (long long)blockIdx.z * sB;
    if (SPLIT_OUT) { Chi += (long long)blockIdx.z * sC; Clo += (long long)blockIdx.z * sC; }
    else           { C   += (long long)blockIdx.z * sC; }

    const int bm = blockIdx.y * BM;
    const int bn = blockIdx.x * BN;
    const int t  = threadIdx.x;
    const int wid  = t >> 5;
    const int lane = t & 31;
    const int g    = lane >> 2;
    const int tig  = lane & 3;
    const int wm = (wid >> 2) * 64;   // 2 m-groups
    const int wn = (wid & 3) * 32;    // 4 n-groups

    const bf16* Abh = Ah + (long long)bm * K;
    const bf16* Abl = Al + (long long)bm * K;
    const bf16* Bbh = Bh + (long long)bn * K;
    const bf16* Bbl = Bl + (long long)bn * K;
    const int T = K / KT;

    // layout per stage: [Ahi | Alo | Bhi | Blo], each 128 rows x APITCH
    auto load_tile = [&](int kt, int s) {
        uint32_t st = smb + s * STAGE_BYTES;
#pragma unroll
        for (int i = 0; i < 4; i++) {
            int id = t + i * 256;      // 0..1023
            int r = id >> 3;           // 0..127
            int c = id & 3;            // chunk 0..3  (id bit2 selects hi/lo below)
            int lohalf = (id >> 2) & 1;
            long long srcA = kt * KT + (long long)r * K + c * 8;
            uint32_t dst = st + lohalf * REGA + r * APITCH + c * 16;
            // interleave: half the ids load hi, half lo, for both A and B
            cp16(dst, (lohalf ? Abl : Abh) + srcA);
            cp16(dst + 2 * REGA, (lohalf ? Bbl : Bbh) + srcA);
        }
    };

    load_tile(0, 0);
    asm volatile("cp.async.commit_group;" ::: "memory");
    load_tile(1, 1);
    asm volatile("cp.async.commit_group;" ::: "memory");

    float acc[4][4][4];
#pragma unroll
    for (int mt = 0; mt < 4; mt++)
#pragma unroll
        for (int nt = 0; nt < 4; nt++)
#pragma unroll
            for (int r = 0; r < 4; r++) acc[mt][nt][r] = 0.f;

    const uint32_t a_off = (wm + (lane & 15)) * APITCH + (lane >> 4) * 16;
    // paired B LDSM4: one x4 covers 16 n-rows x k16 (two 8-col mma B frags)
    const uint32_t b_off = 2 * REGA + (wn + (lane >> 4) * 8 + (lane & 7)) * APITCH
                         + ((lane >> 3) & 1) * 16;

    for (int kt = 0; kt < T; kt++) {
        const int s = kt & 1;
        asm volatile("cp.async.wait_group 1;" ::: "memory");
        __syncthreads();

        const uint32_t st = smb + s * STAGE_BYTES;

#pragma unroll
        for (int ks = 0; ks < 2; ks++) {
            uint32_t ah[4][4], al[4][4], bh[2][4], bl[2][4];
#pragma unroll
            for (int mt = 0; mt < 4; mt++)
                LDSM4(ah[mt], st + a_off + mt * (16 * APITCH) + ks * 32);
#pragma unroll
            for (int mt = 0; mt < 4; mt++)
                LDSM4(al[mt], st + REGA + a_off + mt * (16 * APITCH) + ks * 32);
#pragma unroll
            for (int p = 0; p < 2; p++) {
                LDSM4(bh[p], st + b_off + p * (16 * APITCH) + ks * 32);
                LDSM4(bl[p], st + REGA + b_off + p * (16 * APITCH) + ks * 32);
            }
            // term-outer: same-acc MMAs far apart
#pragma unroll
            for (int p = 0; p < 2; p++)
#pragma unroll
                for (int mt = 0; mt < 4; mt++) {
                    mma16(acc[mt][2 * p],     ah[mt], &bh[p][0]);
                    mma16(acc[mt][2 * p + 1], ah[mt], &bh[p][2]);
                }
#pragma unroll
            for (int p = 0; p < 2; p++)
#pragma unroll
                for (int mt = 0; mt < 4; mt++) {
                    mma16(acc[mt][2 * p],     ah[mt], &bl[p][0]);
                    mma16(acc[mt][2 * p + 1], ah[mt], &bl[p][2]);
                }
#pragma unroll
            for (int p = 0; p < 2; p++)
#pragma unroll
                for (int mt = 0; mt < 4; mt++) {
                    mma16(acc[mt][2 * p],     al[mt], &bh[p][0]);
                    mma16(acc[mt][2 * p + 1], al[mt], &bh[p][2]);
                }
        }

        __syncthreads();                 // all reads of slot s done
        if (kt + 2 < T) load_tile(kt + 2, s);
        asm volatile("cp.async.commit_group;" ::: "memory");   // keep group count aligned
    }

    // ---- epilogue ----
#pragma unroll
    for (int mt = 0; mt < 4; mt++) {
        int r0 = bm + wm + mt * 16 + g;
#pragma unroll
        for (int nt = 0; nt < 4; nt++) {
            int col = bn + wn + nt * 8 + tig * 2;
            float2 v01, v23;
            v01.x = alpha * acc[mt][nt][0];
            v01.y = alpha * acc[mt][nt][1];
            v23.x = alpha * acc[mt][nt][2];
            v23.y = alpha * acc[mt][nt][3];
            if (BIAS) {
                float2 bb = *(const float2*)&bias[col];
                v01.x += bb.x; v01.y += bb.y;
                v23.x += bb.x; v23.y += bb.y;
            }
            if (SPLIT_OUT) {
                uint32_t h2, l2;
                split2(v01.x, v01.y, h2, l2);
                *(uint32_t*)&Chi[(long long)r0 * N + col] = h2;
                *(uint32_t*)&Clo[(long long)r0 * N + col] = l2;
                split2(v23.x, v23.y, h2, l2);
                *(uint32_t*)&Chi[(long long)(r0 + 8) * N + col] = h2;
                *(uint32_t*)&Clo[(long long)(r0 + 8) * N + col] = l2;
            } else {
                *(float2*)&C[(long long)r0 * N + col] = v01;
                *(float2*)&C[(long long)(r0 + 8) * N + col] = v23;
            }
        }
    }
}

// ---------------------------------------------------------------------------
// fp32 -> (hi, lo) bf16 split, 4 elts/thread (x input)
// ---------------------------------------------------------------------------
__global__ void __launch_bounds__(256)
split_x(const float* __restrict__ in, bf16* __restrict__ hi, bf16* __restrict__ lo, int n4)
{
    int i = blockIdx.x * 256 + threadIdx.x;
    if (i >= n4) return;
    float4 v = ((const float4*)in)[i];
    uint32_t h2, l2;
    split2(v.x, v.y, h2, l2);
    ((uint32_t*)hi)[i * 2]     = h2;
    ((uint32_t*)lo)[i * 2]     = l2;
    split2(v.z, v.w, h2, l2);
    ((uint32_t*)hi)[i * 2 + 1] = h2;
    ((uint32_t*)lo)[i * 2 + 1] = l2;
}

// ---------------------------------------------------------------------------
// All four weight matrices split in ONE launch (blockIdx.y selects matrix)
// ---------------------------------------------------------------------------
__global__ void __launch_bounds__(256)
split_w(const float* __restrict__ w0, const float* __restrict__ w1,
        const float* __restrict__ w2, const float* __restrict__ w3,
        bf16* __restrict__ h0, bf16* __restrict__ l0,
        bf16* __restrict__ h1, bf16* __restrict__ l1,
        bf16* __restrict__ h2p, bf16* __restrict__ l2p,
        bf16* __restrict__ h3, bf16* __restrict__ l3)
{
    const float* in;  bf16* hi;  bf16* lo;
    switch (blockIdx.y) {
        case 0: in = w0; hi = h0;  lo = l0;  break;
        case 1: in = w1; hi = h1;  lo = l1;  break;
        case 2: in = w2; hi = h2p; lo = l2p; break;
        default: in = w3; hi = h3; lo = l3;  break;
    }
    int i = blockIdx.x * 256 + threadIdx.x;
    float4 v = ((const float4*)in)[i];
    uint32_t h2, l2;
    split2(v.x, v.y, h2, l2);
    ((uint32_t*)hi)[i * 2]     = h2;
    ((uint32_t*)lo)[i * 2]     = l2;
    split2(v.z, v.w, h2, l2);
    ((uint32_t*)hi)[i * 2 + 1] = h2;
    ((uint32_t*)lo)[i * 2 + 1] = l2;
}

// ---------------------------------------------------------------------------
// v [4096,1024] -> vT [1024,4096] per batch, split to hi/lo at write
// ---------------------------------------------------------------------------
__global__ void __launch_bounds__(256)
transpose_v_split(const float* __restrict__ in, bf16* __restrict__ oh, bf16* __restrict__ ol)
{
    __shared__ float tb[32][33];
    in += (long long)blockIdx.z * 4096 * 1024;
    oh += (long long)blockIdx.z * 4096 * 1024;
    ol += (long long)blockIdx.z * 4096 * 1024;
    int x = blockIdx.x * 32 + threadIdx.x;
    int y = blockIdx.y * 32;
#pragma unroll
    for (int j = 0; j < 32; j += 8)
        tb[threadIdx.y + j][threadIdx.x] = in[(long long)(y + threadIdx.y + j) * 1024 + x];
    __syncthreads();
    int ox = blockIdx.y * 32 + threadIdx.x;
    int oy = blockIdx.x * 32;
#pragma unroll
    for (int j = 0; j < 32; j += 8) {
        float a = tb[threadIdx.x][threadIdx.y + j];
        uint32_t ua = __float_as_uint(a) & 0xFFFF0000u;
        long long idx = (long long)(oy + threadIdx.y + j) * 4096 + ox;
        ((uint16_t*)oh)[idx] = (uint16_t)(ua >> 16);
        ol[idx] = __float2bfloat16_rn(a - __uint_as_float(ua));
    }
}

// ---------------------------------------------------------------------------
// Row softmax over 4096 floats; writes split bf16 weights.
// ---------------------------------------------------------------------------
__global__ void __launch_bounds__(256)
softmax_split(const float* __restrict__ S, bf16* __restrict__ wh, bf16* __restrict__ wl)
{
    const float* row = S + (size_t)blockIdx.x * 4096u;
    const size_t ob = (size_t)blockIdx.x * 4096u;
    const int t = threadIdx.x, lane = t & 31, wid = t >> 5;
    __shared__ float red[8];

    float v[16];
    float m = -3.4e38f;
    const float4* r4 = (const float4*)row;
#pragma unroll
    for (int i = 0; i < 4; i++) {
        float4 val = r4[t + i * 256];
        v[4 * i + 0] = val.x; v[4 * i + 1] = val.y;
        v[4 * i + 2] = val.z; v[4 * i + 3] = val.w;
        m = fmaxf(m, fmaxf(fmaxf(val.x, val.y), fmaxf(val.z, val.w)));
    }
#pragma unroll
    for (int o = 16; o > 0; o >>= 1) m = fmaxf(m, __shfl_xor_sync(0xffffffffu, m, o));
    if (lane == 0) red[wid] = m;
    __syncthreads();
    if (t == 0) {
        float mm = red[0];
#pragma unroll
        for (int i = 1; i < 8; i++) mm = fmaxf(mm, red[i]);
        red[0] = mm;
    }
    __syncthreads();
    m = red[0];
    __syncthreads();

    float s = 0.f;
#pragma unroll
    for (int i = 0; i < 16; i++) { v[i] = __expf(v[i] - m); s += v[i]; }
#pragma unroll
    for (int o = 16; o > 0; o >>= 1) s += __shfl_xor_sync(0xffffffffu, s, o);
    if (lane == 0) red[wid] = s;
    __syncthreads();
    if (t == 0) {
        float ss = red[0];
#pragma unroll
        for (int i = 1; i < 8; i++) ss += red[i];
        red[0] = ss;
    }
    __syncthreads();
    float inv = 1.0f / red[0];

#pragma unroll
    for (int i = 0; i < 4; i++) {
        size_t base = ob + (size_t)(t + i * 256) * 4;
        uint32_t h2, l2;
        split2(v[4 * i + 0] * inv, v[4 * i + 1] * inv, h2, l2);
        *(uint32_t*)&wh[base]     = h2;
        *(uint32_t*)&wl[base]     = l2;
        split2(v[4 * i + 2] * inv, v[4 * i + 3] * inv, h2, l2);
        *(uint32_t*)&wh[base + 2] = h2;
        *(uint32_t*)&wl[base + 2] = l2;
    }
}

// ---------------------------------------------------------------------------
extern "C" void kernel_launch(void* const* d_in, const int* in_sizes, int n_in,
                              void* d_out, int out_size)
{
    const float* x  = (const float*)d_in[0];
    const float* Wq = (const float*)d_in[1];
    const float* bq = (const float*)d_in[2];
    const float* Wk = (const float*)d_in[3];
    const float* bk = (const float*)d_in[4];
    const float* Wv = (const float*)d_in[5];
    const float* bv = (const float*)d_in[6];
    const float* Wo = (const float*)d_in[7];
    const float* bo = (const float*)d_in[8];
    float* out = (float*)d_out;

    float *v, *s;
    bf16 *xh, *xl, *wqh, *wql, *wkh, *wkl, *wvh, *wvl, *woh, *wol;
    bf16 *qh, *ql, *kh, *kl, *vth, *vtl, *wh, *wl, *ah, *al;
    cudaGetSymbolAddress((void**)&v,   g_v);
    cudaGetSymbolAddress((void**)&s,   g_s);
    cudaGetSymbolAddress((void**)&xh,  g_xh);  cudaGetSymbolAddress((void**)&xl,  g_xl);
    cudaGetSymbolAddress((void**)&wqh, g_wqh); cudaGetSymbolAddress((void**)&wql, g_wql);
    cudaGetSymbolAddress((void**)&wkh, g_wkh); cudaGetSymbolAddress((void**)&wkl, g_wkl);
    cudaGetSymbolAddress((void**)&wvh, g_wvh); cudaGetSymbolAddress((void**)&wvl, g_wvl);
    cudaGetSymbolAddress((void**)&woh, g_woh); cudaGetSymbolAddress((void**)&wol, g_wol);
    cudaGetSymbolAddress((void**)&qh,  g_qh);  cudaGetSymbolAddress((void**)&ql,  g_ql);
    cudaGetSymbolAddress((void**)&kh,  g_kh);  cudaGetSymbolAddress((void**)&kl,  g_kl);
    cudaGetSymbolAddress((void**)&vth, g_vth); cudaGetSymbolAddress((void**)&vtl, g_vtl);
    cudaGetSymbolAddress((void**)&wh,  g_wh);  cudaGetSymbolAddress((void**)&wl,  g_wl);
    cudaGetSymbolAddress((void**)&ah,  g_ah);  cudaGetSymbolAddress((void**)&al,  g_al);

    cudaFuncSetAttribute(gemm_b3<true,  true >, cudaFuncAttributeMaxDynamicSharedMemorySize, GEMM_SMEM);
    cudaFuncSetAttribute(gemm_b3<true,  false>, cudaFuncAttributeMaxDynamicSharedMemorySize, GEMM_SMEM);
    cudaFuncSetAttribute(gemm_b3<false, true >, cudaFuncAttributeMaxDynamicSharedMemorySize, GEMM_SMEM);
    cudaFuncSetAttribute(gemm_b3<false, false>, cudaFuncAttributeMaxDynamicSharedMemorySize, GEMM_SMEM);

    const int B = 2, S = 4096, H = 1024;
    const long long qkv = (long long)S * H;
    const long long ss  = (long long)S * S;
    dim3 blk(256);

    // splits (2 launches)
    split_x<<<(B * S * H / 4 + 255) / 256, 256>>>(x, xh, xl, B * S * H / 4);
    split_w<<<dim3(H * H / 4 / 256, 4), 256>>>(Wq, Wk, Wv, Wo,
                                               wqh, wql, wkh, wkl, wvh, wvl, woh, wol);

    // Q/K/V projections
    dim3 gProj(H / BN, (B * S) / BM, 1);
    gemm_b3<true, true ><<<gProj, blk, GEMM_SMEM>>>(xh, xl, wqh, wql, bq, nullptr, qh, ql,
                                                    B * S, H, H, 1.0f, 0, 0, 0);
    gemm_b3<true, true ><<<gProj, blk, GEMM_SMEM>>>(xh, xl, wkh, wkl, bk, nullptr, kh, kl,
                                                    B * S, H, H, 1.0f, 0, 0, 0);
    gemm_b3<true, false><<<gProj, blk, GEMM_SMEM>>>(xh, xl, wvh, wvl, bv, v, nullptr, nullptr,
                                                    B * S, H, H, 1.0f, 0, 0, 0);

    // scores = q @ k^T / 8
    dim3 gSc(S / BN, S / BM, B);
    gemm_b3<false, false><<<gSc, blk, GEMM_SMEM>>>(qh, ql, kh, kl, nullptr, s, nullptr, nullptr,
                                                   S, S, H, 0.125f, qkv, qkv, ss);

    // vT split
    dim3 gT(1024 / 32, 4096 / 32, B);
    transpose_v_split<<<gT, dim3(32, 8)>>>(v, vth, vtl);

    // softmax -> split weights
    softmax_split<<<B * S, 256>>>(s, wh, wl);

    // attn = weights @ vT^T -> split
    dim3 gAt(H / BN, S / BM, B);
    gemm_b3<false, true><<<gAt, blk, GEMM_SMEM>>>(wh, wl, vth, vtl, nullptr, nullptr, ah, al,
                                                  S, H, S, 1.0f, ss, qkv, qkv);

    // out = attn @ Wo^T + bo
    gemm_b3<true, false><<<gProj, blk, GEMM_SMEM>>>(ah, al, woh, wol, bo, out, nullptr, nullptr,
                                                    B * S, H, H, 1.0f, 0, 0, 0);
}

// round 9
// speedup vs baseline: 1.1090x; 1.1090x over previous
#include <cuda_runtime.h>
#include <cuda_bf16.h>
#include <cstdint>

// ---------------------------------------------------------------------------
// DistributedAttention, B=2, S=4096, H=1024 fp32.
// bf16x3 error-compensated mma.sync (a = hi + lo; hi*hi + hi*lo + lo*hi).
// All GEMMs NT: C[M,N] = alpha * A[M,K] @ B[N,K]^T (+bias).
// R9: GEMM = R6 config (CTA 128x256, 8 warps, warp tile 64x64, 3-stage —
//     best measured; HMMA pipe ceiling reached). Softmax exp moved off the
//     MUFU pipe (rt=8) onto FMA via polynomial 2^f — softmax ~240us -> ~55us.
// ---------------------------------------------------------------------------

#define BM 128
#define BN 256
#define KT 32
#define STAGES 3
#define APITCH 80                        // bytes per 32-bf16 row (5x16B, bank-clean)
#define REGA (128 * APITCH)              // 10240
#define REGB (256 * APITCH)              // 20480
#define STAGE_BYTES (2 * REGA + 2 * REGB)  // 61440
#define GEMM_SMEM (STAGES * STAGE_BYTES)   // 184320

typedef __nv_bfloat16 bf16;

// fp32 scratch
__device__ float g_v[8388608];          // v projection (fp32, pre-transpose)
__device__ float g_s[33554432];         // scores (fp32)
// split (hi/lo bf16) scratch
__device__ bf16 g_xh[8388608],  g_xl[8388608];
__device__ bf16 g_wqh[1048576], g_wql[1048576];
__device__ bf16 g_wkh[1048576], g_wkl[1048576];
__device__ bf16 g_wvh[1048576], g_wvl[1048576];
__device__ bf16 g_woh[1048576], g_wol[1048576];
__device__ bf16 g_qh[8388608],  g_ql[8388608];
__device__ bf16 g_kh[8388608],  g_kl[8388608];
__device__ bf16 g_vth[8388608], g_vtl[8388608];
__device__ bf16 g_wh[33554432], g_wl[33554432];   // softmax weights
__device__ bf16 g_ah[8388608],  g_al[8388608];    // attn output

__device__ __forceinline__ uint32_t smem_u32(const void* p) {
    uint32_t a;
    asm("{ .reg .u64 t; cvta.to.shared.u64 t, %1; cvt.u32.u64 %0, t; }" : "=r"(a) : "l"(p));
    return a;
}
__device__ __forceinline__ void cp16(uint32_t dst, const void* src) {
    asm volatile("cp.async.cg.shared.global [%0], [%1], 16;" :: "r"(dst), "l"(src));
}

#define LDSM4(r, addr) \
    asm volatile("ldmatrix.sync.aligned.m8n8.x4.shared.b16 {%0,%1,%2,%3}, [%4];" \
                 : "=r"((r)[0]), "=r"((r)[1]), "=r"((r)[2]), "=r"((r)[3]) : "r"(addr))

__device__ __forceinline__ void mma16(float* c, const uint32_t* a, const uint32_t* b) {
    asm volatile(
        "mma.sync.aligned.m16n8k16.row.col.f32.bf16.bf16.f32 "
        "{%0,%1,%2,%3}, {%4,%5,%6,%7}, {%8,%9}, {%0,%1,%2,%3};"
        : "+f"(c[0]), "+f"(c[1]), "+f"(c[2]), "+f"(c[3])
        : "r"(a[0]), "r"(a[1]), "r"(a[2]), "r"(a[3]), "r"(b[0]), "r"(b[1]));
}

// split pair (a=low element, b=high element) into packed bf16x2 hi / lo words
__device__ __forceinline__ void split2(float a, float b, uint32_t& hi2, uint32_t& lo2) {
    uint32_t ua = __float_as_uint(a) & 0xFFFF0000u;
    uint32_t ub = __float_as_uint(b) & 0xFFFF0000u;
    hi2 = (ua >> 16) | ub;
    __nv_bfloat162 l2 = __floats2bfloat162_rn(a - __uint_as_float(ua),
                                              b - __uint_as_float(ub));
    lo2 = *reinterpret_cast<uint32_t*>(&l2);
}

// FMA-pipe exp(x) for x <= 0: 2^(x*log2e) via rint + degree-6 Taylor (no MUFU).
__device__ __forceinline__ float fexp(float x) {
    float y = fmaxf(x * 1.4426950408889634f, -120.0f);
    float n = rintf(y);
    float f = y - n;                      // [-0.5, 0.5]
    float p = 1.5403531e-4f;
    p = fmaf(p, f, 1.3333558e-3f);
    p = fmaf(p, f, 9.6181291e-3f);
    p = fmaf(p, f, 5.5504109e-2f);
    p = fmaf(p, f, 2.4022651e-1f);
    p = fmaf(p, f, 6.9314718e-1f);
    p = fmaf(p, f, 1.0f);
    int i = (int)n;
    float sc = __uint_as_float((uint32_t)(i + 127) << 23);
    return p * sc;
}

// ---------------------------------------------------------------------------
// bf16x3 NT GEMM. 256 threads, CTA 128x256, warp grid 2(m) x 4(n),
// warp tile 64x64. 3-stage cp.async pipeline.  (R6 config — best measured.)
// ---------------------------------------------------------------------------
template <bool BIAS, bool SPLIT_OUT>
__global__ void __launch_bounds__(256, 1)
gemm_b3(const bf16* __restrict__ Ah, const bf16* __restrict__ Al,
        const bf16* __restrict__ Bh, const bf16* __restrict__ Bl,
        const float* __restrict__ bias, float* __restrict__ C,
        bf16* __restrict__ Chi, bf16* __restrict__ Clo,
        int M, int N, int K, float alpha,
        long long sA, long long sB, long long sC)
{
    extern __shared__ char sm[];
    const uint32_t smb = smem_u32(sm);

    Ah += (long long)blockIdx.z * sA;  Al += (long long)blockIdx.z * sA;
    Bh += (long long)blockIdx.z * sB;  Bl += (long long)blockIdx.z * sB;
    if (SPLIT_OUT) { Chi += (long long)blockIdx.z * sC; Clo += (long long)blockIdx.z * sC; }
    else           { C   += (long long)blockIdx.z * sC; }

    const int bm = blockIdx.y * BM;
    const int bn = blockIdx.x * BN;
    const int t  = threadIdx.x;
    const int wid  = t >> 5;
    const int lane = t & 31;
    const int g    = lane >> 2;
    const int tig  = lane & 3;
    const int wm = (wid >> 2) * 64;   // 2 m-groups
    const int wn = (wid & 3) * 64;    // 4 n-groups

    const bf16* Abh = Ah + (long long)bm * K;
    const bf16* Abl = Al + (long long)bm * K;
    const bf16* Bbh = Bh + (long long)bn * K;
    const bf16* Bbl = Bl + (long long)bn * K;
    const int T = K / KT;

    auto load_tile = [&](int kt, int s) {
        uint32_t st = smb + s * STAGE_BYTES;
#pragma unroll
        for (int j = 0; j < 4; j++) {
            int rem = t + (j & 1) * 256;           // 0..511
            int r = rem >> 2, c = rem & 3;
            const bf16* src = ((j >> 1) ? Abl : Abh) + kt * KT + (long long)r * K + c * 8;
            cp16(st + (j >> 1) * REGA + r * APITCH + c * 16, src);
        }
#pragma unroll
        for (int j = 0; j < 8; j++) {
            int rem = t + (j & 3) * 256;           // 0..1023
            int r = rem >> 2, c = rem & 3;
            const bf16* src = ((j >> 2) ? Bbl : Bbh) + kt * KT + (long long)r * K + c * 8;
            cp16(st + 2 * REGA + (j >> 2) * REGB + r * APITCH + c * 16, src);
        }
    };

    load_tile(0, 0);
    asm volatile("cp.async.commit_group;" ::: "memory");
    load_tile(1, 1);
    asm volatile("cp.async.commit_group;" ::: "memory");

    float acc[4][8][4];
#pragma unroll
    for (int mt = 0; mt < 4; mt++)
#pragma unroll
        for (int nt = 0; nt < 8; nt++)
#pragma unroll
            for (int r = 0; r < 4; r++) acc[mt][nt][r] = 0.f;

    const uint32_t a_off = (wm + (lane & 15)) * APITCH + (lane >> 4) * 16;
    const uint32_t b_off = 2 * REGA + (wn + (lane >> 4) * 8 + (lane & 7)) * APITCH
                         + ((lane >> 3) & 1) * 16;

    int s_cur = 0;
    for (int kt = 0; kt < T; kt++) {
        asm volatile("cp.async.wait_group 1;" ::: "memory");
        __syncthreads();

        const uint32_t st = smb + s_cur * STAGE_BYTES;

#pragma unroll
        for (int ks = 0; ks < 2; ks++) {
            uint32_t ah[4][4], al[4][4];
#pragma unroll
            for (int mt = 0; mt < 4; mt++)
                LDSM4(ah[mt], st + a_off + mt * (16 * APITCH) + ks * 32);
#pragma unroll
            for (int mt = 0; mt < 4; mt++)
                LDSM4(al[mt], st + REGA + a_off + mt * (16 * APITCH) + ks * 32);

            uint32_t bh[2][4], bl[2][4];
            LDSM4(bh[0], st + b_off + ks * 32);
            LDSM4(bl[0], st + REGB + b_off + ks * 32);
#pragma unroll
            for (int p = 0; p < 4; p++) {
                int cur = p & 1, nxt = cur ^ 1;
                if (p < 3) {
                    LDSM4(bh[nxt], st + b_off + (p + 1) * (16 * APITCH) + ks * 32);
                    LDSM4(bl[nxt], st + REGB + b_off + (p + 1) * (16 * APITCH) + ks * 32);
                }
#pragma unroll
                for (int mt = 0; mt < 4; mt++) {
                    mma16(acc[mt][2 * p],     ah[mt], &bh[cur][0]);
                    mma16(acc[mt][2 * p + 1], ah[mt], &bh[cur][2]);
                }
#pragma unroll
                for (int mt = 0; mt < 4; mt++) {
                    mma16(acc[mt][2 * p],     ah[mt], &bl[cur][0]);
                    mma16(acc[mt][2 * p + 1], ah[mt], &bl[cur][2]);
                }
#pragma unroll
                for (int mt = 0; mt < 4; mt++) {
                    mma16(acc[mt][2 * p],     al[mt], &bh[cur][0]);
                    mma16(acc[mt][2 * p + 1], al[mt], &bh[cur][2]);
                }
            }
        }

        int pf = kt + 2;
        if (pf < T) {
            int s_pf = s_cur + 2; if (s_pf >= 3) s_pf -= 3;
            load_tile(pf, s_pf);
        }
        asm volatile("cp.async.commit_group;" ::: "memory");
        s_cur = s_cur + 1; if (s_cur >= 3) s_cur -= 3;
    }

    // ---- epilogue ----
#pragma unroll
    for (int mt = 0; mt < 4; mt++) {
        int r0 = bm + wm + mt * 16 + g;
#pragma unroll
        for (int nt = 0; nt < 8; nt++) {
            int col = bn + wn + nt * 8 + tig * 2;
            float2 v01, v23;
            v01.x = alpha * acc[mt][nt][0];
            v01.y = alpha * acc[mt][nt][1];
            v23.x = alpha * acc[mt][nt][2];
            v23.y = alpha * acc[mt][nt][3];
            if (BIAS) {
                float2 bb = *(const float2*)&bias[col];
                v01.x += bb.x; v01.y += bb.y;
                v23.x += bb.x; v23.y += bb.y;
            }
            if (SPLIT_OUT) {
                uint32_t h2, l2;
                split2(v01.x, v01.y, h2, l2);
                *(uint32_t*)&Chi[(long long)r0 * N + col] = h2;
                *(uint32_t*)&Clo[(long long)r0 * N + col] = l2;
                split2(v23.x, v23.y, h2, l2);
                *(uint32_t*)&Chi[(long long)(r0 + 8) * N + col] = h2;
                *(uint32_t*)&Clo[(long long)(r0 + 8) * N + col] = l2;
            } else {
                *(float2*)&C[(long long)r0 * N + col] = v01;
                *(float2*)&C[(long long)(r0 + 8) * N + col] = v23;
            }
        }
    }
}

// ---------------------------------------------------------------------------
// fp32 -> (hi, lo) bf16 split, 4 elts/thread (x input)
// ---------------------------------------------------------------------------
__global__ void __launch_bounds__(256)
split_x(const float* __restrict__ in, bf16* __restrict__ hi, bf16* __restrict__ lo, int n4)
{
    int i = blockIdx.x * 256 + threadIdx.x;
    if (i >= n4) return;
    float4 v = ((const float4*)in)[i];
    uint32_t h2, l2;
    split2(v.x, v.y, h2, l2);
    ((uint32_t*)hi)[i * 2]     = h2;
    ((uint32_t*)lo)[i * 2]     = l2;
    split2(v.z, v.w, h2, l2);
    ((uint32_t*)hi)[i * 2 + 1] = h2;
    ((uint32_t*)lo)[i * 2 + 1] = l2;
}

// ---------------------------------------------------------------------------
// All four weight matrices split in ONE launch (blockIdx.y selects matrix)
// ---------------------------------------------------------------------------
__global__ void __launch_bounds__(256)
split_w(const float* __restrict__ w0, const float* __restrict__ w1,
        const float* __restrict__ w2, const float* __restrict__ w3,
        bf16* __restrict__ h0, bf16* __restrict__ l0,
        bf16* __restrict__ h1, bf16* __restrict__ l1,
        bf16* __restrict__ h2p, bf16* __restrict__ l2p,
        bf16* __restrict__ h3, bf16* __restrict__ l3)
{
    const float* in;  bf16* hi;  bf16* lo;
    switch (blockIdx.y) {
        case 0: in = w0; hi = h0;  lo = l0;  break;
        case 1: in = w1; hi = h1;  lo = l1;  break;
        case 2: in = w2; hi = h2p; lo = l2p; break;
        default: in = w3; hi = h3; lo = l3;  break;
    }
    int i = blockIdx.x * 256 + threadIdx.x;
    float4 v = ((const float4*)in)[i];
    uint32_t h2, l2;
    split2(v.x, v.y, h2, l2);
    ((uint32_t*)hi)[i * 2]     = h2;
    ((uint32_t*)lo)[i * 2]     = l2;
    split2(v.z, v.w, h2, l2);
    ((uint32_t*)hi)[i * 2 + 1] = h2;
    ((uint32_t*)lo)[i * 2 + 1] = l2;
}

// ---------------------------------------------------------------------------
// v [4096,1024] -> vT [1024,4096] per batch, split to hi/lo at write
// ---------------------------------------------------------------------------
__global__ void __launch_bounds__(256)
transpose_v_split(const float* __restrict__ in, bf16* __restrict__ oh, bf16* __restrict__ ol)
{
    __shared__ float tb[32][33];
    in += (long long)blockIdx.z * 4096 * 1024;
    oh += (long long)blockIdx.z * 4096 * 1024;
    ol += (long long)blockIdx.z * 4096 * 1024;
    int x = blockIdx.x * 32 + threadIdx.x;
    int y = blockIdx.y * 32;
#pragma unroll
    for (int j = 0; j < 32; j += 8)
        tb[threadIdx.y + j][threadIdx.x] = in[(long long)(y + threadIdx.y + j) * 1024 + x];
    __syncthreads();
    int ox = blockIdx.y * 32 + threadIdx.x;
    int oy = blockIdx.x * 32;
#pragma unroll
    for (int j = 0; j < 32; j += 8) {
        float a = tb[threadIdx.x][threadIdx.y + j];
        uint32_t ua = __float_as_uint(a) & 0xFFFF0000u;
        long long idx = (long long)(oy + threadIdx.y + j) * 4096 + ox;
        ((uint16_t*)oh)[idx] = (uint16_t)(ua >> 16);
        ol[idx] = __float2bfloat16_rn(a - __uint_as_float(ua));
    }
}

// ---------------------------------------------------------------------------
// Row softmax over 4096 floats; FMA-pipe exp; writes split bf16 weights.
// ---------------------------------------------------------------------------
__global__ void __launch_bounds__(256)
softmax_split(const float* __restrict__ S, bf16* __restrict__ wh, bf16* __restrict__ wl)
{
    const float* row = S + (size_t)blockIdx.x * 4096u;
    const size_t ob = (size_t)blockIdx.x * 4096u;
    const int t = threadIdx.x, lane = t & 31, wid = t >> 5;
    __shared__ float red[8];

    float v[16];
    float m = -3.4e38f;
    const float4* r4 = (const float4*)row;
#pragma unroll
    for (int i = 0; i < 4; i++) {
        float4 val = r4[t + i * 256];
        v[4 * i + 0] = val.x; v[4 * i + 1] = val.y;
        v[4 * i + 2] = val.z; v[4 * i + 3] = val.w;
        m = fmaxf(m, fmaxf(fmaxf(val.x, val.y), fmaxf(val.z, val.w)));
    }
#pragma unroll
    for (int o = 16; o > 0; o >>= 1) m = fmaxf(m, __shfl_xor_sync(0xffffffffu, m, o));
    if (lane == 0) red[wid] = m;
    __syncthreads();
    if (t == 0) {
        float mm = red[0];
#pragma unroll
        for (int i = 1; i < 8; i++) mm = fmaxf(mm, red[i]);
        red[0] = mm;
    }
    __syncthreads();
    m = red[0];
    __syncthreads();

    float s = 0.f;
#pragma unroll
    for (int i = 0; i < 16; i++) { v[i] = fexp(v[i] - m); s += v[i]; }
#pragma unroll
    for (int o = 16; o > 0; o >>= 1) s += __shfl_xor_sync(0xffffffffu, s, o);
    if (lane == 0) red[wid] = s;
    __syncthreads();
    if (t == 0) {
        float ss = red[0];
#pragma unroll
        for (int i = 1; i < 8; i++) ss += red[i];
        red[0] = ss;
    }
    __syncthreads();
    float inv = 1.0f / red[0];

#pragma unroll
    for (int i = 0; i < 4; i++) {
        size_t base = ob + (size_t)(t + i * 256) * 4;
        uint32_t h2, l2;
        split2(v[4 * i + 0] * inv, v[4 * i + 1] * inv, h2, l2);
        *(uint32_t*)&wh[base]     = h2;
        *(uint32_t*)&wl[base]     = l2;
        split2(v[4 * i + 2] * inv, v[4 * i + 3] * inv, h2, l2);
        *(uint32_t*)&wh[base + 2] = h2;
        *(uint32_t*)&wl[base + 2] = l2;
    }
}

// ---------------------------------------------------------------------------
extern "C" void kernel_launch(void* const* d_in, const int* in_sizes, int n_in,
                              void* d_out, int out_size)
{
    const float* x  = (const float*)d_in[0];
    const float* Wq = (const float*)d_in[1];
    const float* bq = (const float*)d_in[2];
    const float* Wk = (const float*)d_in[3];
    const float* bk = (const float*)d_in[4];
    const float* Wv = (const float*)d_in[5];
    const float* bv = (const float*)d_in[6];
    const float* Wo = (const float*)d_in[7];
    const float* bo = (const float*)d_in[8];
    float* out = (float*)d_out;

    float *v, *s;
    bf16 *xh, *xl, *wqh, *wql, *wkh, *wkl, *wvh, *wvl, *woh, *wol;
    bf16 *qh, *ql, *kh, *kl, *vth, *vtl, *wh, *wl, *ah, *al;
    cudaGetSymbolAddress((void**)&v,   g_v);
    cudaGetSymbolAddress((void**)&s,   g_s);
    cudaGetSymbolAddress((void**)&xh,  g_xh);  cudaGetSymbolAddress((void**)&xl,  g_xl);
    cudaGetSymbolAddress((void**)&wqh, g_wqh); cudaGetSymbolAddress((void**)&wql, g_wql);
    cudaGetSymbolAddress((void**)&wkh, g_wkh); cudaGetSymbolAddress((void**)&wkl, g_wkl);
    cudaGetSymbolAddress((void**)&wvh, g_wvh); cudaGetSymbolAddress((void**)&wvl, g_wvl);
    cudaGetSymbolAddress((void**)&woh, g_woh); cudaGetSymbolAddress((void**)&wol, g_wol);
    cudaGetSymbolAddress((void**)&qh,  g_qh);  cudaGetSymbolAddress((void**)&ql,  g_ql);
    cudaGetSymbolAddress((void**)&kh,  g_kh);  cudaGetSymbolAddress((void**)&kl,  g_kl);
    cudaGetSymbolAddress((void**)&vth, g_vth); cudaGetSymbolAddress((void**)&vtl, g_vtl);
    cudaGetSymbolAddress((void**)&wh,  g_wh);  cudaGetSymbolAddress((void**)&wl,  g_wl);
    cudaGetSymbolAddress((void**)&ah,  g_ah);  cudaGetSymbolAddress((void**)&al,  g_al);

    cudaFuncSetAttribute(gemm_b3<true,  true >, cudaFuncAttributeMaxDynamicSharedMemorySize, GEMM_SMEM);
    cudaFuncSetAttribute(gemm_b3<true,  false>, cudaFuncAttributeMaxDynamicSharedMemorySize, GEMM_SMEM);
    cudaFuncSetAttribute(gemm_b3<false, true >, cudaFuncAttributeMaxDynamicSharedMemorySize, GEMM_SMEM);
    cudaFuncSetAttribute(gemm_b3<false, false>, cudaFuncAttributeMaxDynamicSharedMemorySize, GEMM_SMEM);

    const int B = 2, S = 4096, H = 1024;
    const long long qkv = (long long)S * H;
    const long long ss  = (long long)S * S;
    dim3 blk(256);

    // splits (2 launches)
    split_x<<<(B * S * H / 4 + 255) / 256, 256>>>(x, xh, xl, B * S * H / 4);
    split_w<<<dim3(H * H / 4 / 256, 4), 256>>>(Wq, Wk, Wv, Wo,
                                               wqh, wql, wkh, wkl, wvh, wvl, woh, wol);

    // Q/K/V projections
    dim3 gProj(H / BN, (B * S) / BM, 1);
    gemm_b3<true, true ><<<gProj, blk, GEMM_SMEM>>>(xh, xl, wqh, wql, bq, nullptr, qh, ql,
                                                    B * S, H, H, 1.0f, 0, 0, 0);
    gemm_b3<true, true ><<<gProj, blk, GEMM_SMEM>>>(xh, xl, wkh, wkl, bk, nullptr, kh, kl,
                                                    B * S, H, H, 1.0f, 0, 0, 0);
    gemm_b3<true, false><<<gProj, blk, GEMM_SMEM>>>(xh, xl, wvh, wvl, bv, v, nullptr, nullptr,
                                                    B * S, H, H, 1.0f, 0, 0, 0);

    // scores = q @ k^T / 8
    dim3 gSc(S / BN, S / BM, B);
    gemm_b3<false, false><<<gSc, blk, GEMM_SMEM>>>(qh, ql, kh, kl, nullptr, s, nullptr, nullptr,
                                                   S, S, H, 0.125f, qkv, qkv, ss);

    // vT split
    dim3 gT(1024 / 32, 4096 / 32, B);
    transpose_v_split<<<gT, dim3(32, 8)>>>(v, vth, vtl);

    // softmax -> split weights (FMA-pipe exp)
    softmax_split<<<B * S, 256>>>(s, wh, wl);

    // attn = weights @ vT^T -> split
    dim3 gAt(H / BN, S / BM, B);
    gemm_b3<false, true><<<gAt, blk, GEMM_SMEM>>>(wh, wl, vth, vtl, nullptr, nullptr, ah, al,
                                                  S, H, S, 1.0f, ss, qkv, qkv);

    // out = attn @ Wo^T + bo
    gemm_b3<true, false><<<gProj, blk, GEMM_SMEM>>>(ah, al, woh, wol, bo, out, nullptr, nullptr,
                                                    B * S, H, H, 1.0f, 0, 0, 0);
}